// round 13
// baseline (speedup 1.0000x reference)
#include <cuda_runtime.h>
#include <math.h>

// ---------------------------------------------------------------------------
// R13: R5's 16-points/thread shape, fixed. R5 failed because ptxas (without a
// min-blocks hint) chose 32 regs and spilled the 48-float working set.
// __launch_bounds__(256, 3) raises the register budget to ~85/thread so all
// 6 front-batched 256-bit loads stay live in registers (MLP=6, zero spill).
// L2 policies: el loads / ef stores (best measured combination, R3).
// Grid stays large/one-shot: big-grid LDG kernels have the smallest
// steady-state replay penalty (R12 gap analysis).
// ---------------------------------------------------------------------------
struct V8 { unsigned r0, r1, r2, r3, r4, r5, r6, r7; };

__device__ __forceinline__ V8 ldg256_el(const void* p) {
    V8 v;
    asm volatile("ld.global.nc.L2::evict_last.v8.b32 "
                 "{%0,%1,%2,%3,%4,%5,%6,%7}, [%8];"
                 : "=r"(v.r0), "=r"(v.r1), "=r"(v.r2), "=r"(v.r3),
                   "=r"(v.r4), "=r"(v.r5), "=r"(v.r6), "=r"(v.r7)
                 : "l"(p));
    return v;
}
__device__ __forceinline__ void stg256_ef(void* p, const float* g) {
    asm volatile("st.global.L2::evict_first.v8.b32 "
                 "[%0], {%1,%2,%3,%4,%5,%6,%7,%8};"
                 :: "l"(p),
                    "r"(__float_as_uint(g[0])), "r"(__float_as_uint(g[1])),
                    "r"(__float_as_uint(g[2])), "r"(__float_as_uint(g[3])),
                    "r"(__float_as_uint(g[4])), "r"(__float_as_uint(g[5])),
                    "r"(__float_as_uint(g[6])), "r"(__float_as_uint(g[7]))
                 : "memory");
}
__device__ __forceinline__ void unpack8(const V8& v, float* f) {
    f[0] = __uint_as_float(v.r0); f[1] = __uint_as_float(v.r1);
    f[2] = __uint_as_float(v.r2); f[3] = __uint_as_float(v.r3);
    f[4] = __uint_as_float(v.r4); f[5] = __uint_as_float(v.r5);
    f[6] = __uint_as_float(v.r6); f[7] = __uint_as_float(v.r7);
}

// ---------------------------------------------------------------------------
// Fused kernel: thread 0 per block computes the SE(3) exp map in fp32
// (~1e-6 of the 1e-3 budget), broadcasts R|t via smem. Each thread
// transforms 16 points via 6 front-batched 256-bit loads + 6 stores.
// ---------------------------------------------------------------------------
__global__ void __launch_bounds__(256, 3)
se3_kernel16(const float* __restrict__ pose,
             const char* __restrict__ xb, char* __restrict__ ob,
             int n_hex,
             const float* __restrict__ x_tail, float* __restrict__ o_tail,
             int n_tail) {
    __shared__ float sRt[12];

    if (threadIdx.x == 0) {
        float tx = pose[0], ty = pose[1], tz = pose[2];
        float px = pose[3], py = pose[4], pz = pose[5];
        float th2 = px * px + py * py + pz * pz;
        float A, B, C;
        if (th2 < 1e-8f) {
            A = 1.0f - th2 / 6.0f;
            B = 0.5f - th2 / 24.0f;
            C = 1.0f / 6.0f - th2 / 120.0f;
        } else {
            float th = sqrtf(th2);
            float s = sinf(th), c = cosf(th);
            A = s / th;
            B = (1.0f - c) / th2;
            C = (th - s) / (th2 * th);
        }
        // Phi^2 = phi*phi^T - th2*I (skew-symmetric identity)
        sRt[0] = 1.0f + B * (px * px - th2);
        sRt[1] = -A * pz + B * px * py;
        sRt[2] =  A * py + B * px * pz;
        sRt[3] =  A * pz + B * px * py;
        sRt[4] = 1.0f + B * (py * py - th2);
        sRt[5] = -A * px + B * py * pz;
        sRt[6] = -A * py + B * px * pz;
        sRt[7] =  A * px + B * py * pz;
        sRt[8] = 1.0f + B * (pz * pz - th2);

        float V0 = 1.0f + C * (px * px - th2);
        float V1 = -B * pz + C * px * py;
        float V2 =  B * py + C * px * pz;
        float V3 =  B * pz + C * px * py;
        float V4 = 1.0f + C * (py * py - th2);
        float V5 = -B * px + C * py * pz;
        float V6 = -B * py + C * px * pz;
        float V7 =  B * px + C * py * pz;
        float V8v = 1.0f + C * (pz * pz - th2);

        sRt[9]  = V0 * tx + V1 * ty + V2 * tz;
        sRt[10] = V3 * tx + V4 * ty + V5 * tz;
        sRt[11] = V6 * tx + V7 * ty + V8v * tz;
    }
    __syncthreads();

    float Rt[12];
    #pragma unroll
    for (int k = 0; k < 12; k++) Rt[k] = sRt[k];

    int i = blockIdx.x * blockDim.x + threadIdx.x;

    if (i < n_hex) {
        const char* p = xb + (size_t)192 * i;
        // Front-batch all 6 x 256-bit loads (MLP = 6; regs budgeted for it).
        V8 v0 = ldg256_el(p);
        V8 v1 = ldg256_el(p + 32);
        V8 v2 = ldg256_el(p + 64);
        V8 v3 = ldg256_el(p + 96);
        V8 v4 = ldg256_el(p + 128);
        V8 v5 = ldg256_el(p + 160);

        float f[48];
        unpack8(v0, f);      unpack8(v1, f + 8);  unpack8(v2, f + 16);
        unpack8(v3, f + 24); unpack8(v4, f + 32); unpack8(v5, f + 40);

        float g[48];
        #pragma unroll
        for (int k = 0; k < 16; k++) {
            float X = f[3 * k], Y = f[3 * k + 1], Z = f[3 * k + 2];
            g[3 * k + 0] = fmaf(Rt[0], X, fmaf(Rt[1], Y, fmaf(Rt[2], Z, Rt[9])));
            g[3 * k + 1] = fmaf(Rt[3], X, fmaf(Rt[4], Y, fmaf(Rt[5], Z, Rt[10])));
            g[3 * k + 2] = fmaf(Rt[6], X, fmaf(Rt[7], Y, fmaf(Rt[8], Z, Rt[11])));
        }

        char* q = ob + (size_t)192 * i;
        stg256_ef(q,       g);
        stg256_ef(q + 32,  g + 8);
        stg256_ef(q + 64,  g + 16);
        stg256_ef(q + 96,  g + 24);
        stg256_ef(q + 128, g + 32);
        stg256_ef(q + 160, g + 40);
    } else if (i == n_hex && n_tail > 0) {
        // Scalar tail (N % 16 points); dead for N = 8388608 but general.
        for (int k = 0; k < n_tail; k++) {
            int base = (n_hex * 16 + k) * 3;
            float X = x_tail[base + 0], Y = x_tail[base + 1],
                  Z = x_tail[base + 2];
            o_tail[base + 0] = fmaf(Rt[0], X, fmaf(Rt[1], Y, fmaf(Rt[2], Z, Rt[9])));
            o_tail[base + 1] = fmaf(Rt[3], X, fmaf(Rt[4], Y, fmaf(Rt[5], Z, Rt[10])));
            o_tail[base + 2] = fmaf(Rt[6], X, fmaf(Rt[7], Y, fmaf(Rt[8], Z, Rt[11])));
        }
    }
}

// ---------------------------------------------------------------------------
// Launch: flat one-shot grid (2049 blocks).
// ---------------------------------------------------------------------------
extern "C" void kernel_launch(void* const* d_in, const int* in_sizes, int n_in,
                              void* d_out, int out_size) {
    const float* pose = (const float*)d_in[0];  // (1, 6)
    const float* x    = (const float*)d_in[1];  // (N, 3)
    float* out = (float*)d_out;

    int n_points = in_sizes[1] / 3;
    int n_hex    = n_points / 16;
    int n_tail   = n_points % 16;

    const int threads = 256;
    int blocks = (n_hex + 1 + threads - 1) / threads;  // +1 thread for tail

    se3_kernel16<<<blocks, threads>>>(
        pose, (const char*)x, (char*)out, n_hex, x, out, n_tail);
}

// round 14
// speedup vs baseline: 1.1188x; 1.1188x over previous
#include <cuda_runtime.h>
#include <math.h>

// ---------------------------------------------------------------------------
// FINAL (confirmation re-bench of the R3 champion, 36.0us).
// 13 rounds of structural alternatives (MLP 3/6/16-pt shapes, persistent
// grids, full-TMA, TMA+STG hybrid, 5 L2 policy configs, write-through) all
// measured equal or worse in steady state: back-to-back graph replays pin
// the mixed read/write stream at ~5.7TB/s, so dur_us floors at
// 192MB compulsory traffic / 5.7TB/s + ~2us overhead ~= 36us. This kernel
// sits on that floor.
//   - fused single launch; thread 0/block computes SE(3) exp map in fp32
//     (rel_err 6.1e-8 measured, budget 1e-3), smem-broadcast of R|t
//   - 8 points/thread: 3 front-batched LDG.256 (L2::evict_last) +
//     24 FMA triplets + 3 STG.256 (L2::evict_first)
//   - flat one-shot 4097-block grid (best steady-state replay behavior)
// ---------------------------------------------------------------------------
struct V8 { unsigned r0, r1, r2, r3, r4, r5, r6, r7; };

__device__ __forceinline__ V8 ldg256_el(const void* p) {
    V8 v;
    asm volatile("ld.global.nc.L2::evict_last.v8.b32 "
                 "{%0,%1,%2,%3,%4,%5,%6,%7}, [%8];"
                 : "=r"(v.r0), "=r"(v.r1), "=r"(v.r2), "=r"(v.r3),
                   "=r"(v.r4), "=r"(v.r5), "=r"(v.r6), "=r"(v.r7)
                 : "l"(p));
    return v;
}
__device__ __forceinline__ void stg256_ef(void* p, const float* g) {
    asm volatile("st.global.L2::evict_first.v8.b32 "
                 "[%0], {%1,%2,%3,%4,%5,%6,%7,%8};"
                 :: "l"(p),
                    "r"(__float_as_uint(g[0])), "r"(__float_as_uint(g[1])),
                    "r"(__float_as_uint(g[2])), "r"(__float_as_uint(g[3])),
                    "r"(__float_as_uint(g[4])), "r"(__float_as_uint(g[5])),
                    "r"(__float_as_uint(g[6])), "r"(__float_as_uint(g[7]))
                 : "memory");
}

__global__ void __launch_bounds__(256)
se3_fused_kernel(const float* __restrict__ pose,
                 const char* __restrict__ xb, char* __restrict__ ob,
                 int n_oct,
                 const float* __restrict__ x_tail, float* __restrict__ o_tail,
                 int n_tail) {
    __shared__ float sRt[12];

    if (threadIdx.x == 0) {
        float tx = pose[0], ty = pose[1], tz = pose[2];
        float px = pose[3], py = pose[4], pz = pose[5];
        float th2 = px * px + py * py + pz * pz;
        float A, B, C;
        if (th2 < 1e-8f) {
            A = 1.0f - th2 / 6.0f;
            B = 0.5f - th2 / 24.0f;
            C = 1.0f / 6.0f - th2 / 120.0f;
        } else {
            float th = sqrtf(th2);
            float s = sinf(th), c = cosf(th);
            A = s / th;
            B = (1.0f - c) / th2;
            C = (th - s) / (th2 * th);
        }
        // Phi^2 = phi*phi^T - th2*I (skew-symmetric identity)
        sRt[0] = 1.0f + B * (px * px - th2);
        sRt[1] = -A * pz + B * px * py;
        sRt[2] =  A * py + B * px * pz;
        sRt[3] =  A * pz + B * px * py;
        sRt[4] = 1.0f + B * (py * py - th2);
        sRt[5] = -A * px + B * py * pz;
        sRt[6] = -A * py + B * px * pz;
        sRt[7] =  A * px + B * py * pz;
        sRt[8] = 1.0f + B * (pz * pz - th2);

        float V0 = 1.0f + C * (px * px - th2);
        float V1 = -B * pz + C * px * py;
        float V2 =  B * py + C * px * pz;
        float V3 =  B * pz + C * px * py;
        float V4 = 1.0f + C * (py * py - th2);
        float V5 = -B * px + C * py * pz;
        float V6 = -B * py + C * px * pz;
        float V7 =  B * px + C * py * pz;
        float V8v = 1.0f + C * (pz * pz - th2);

        sRt[9]  = V0 * tx + V1 * ty + V2 * tz;
        sRt[10] = V3 * tx + V4 * ty + V5 * tz;
        sRt[11] = V6 * tx + V7 * ty + V8v * tz;
    }
    __syncthreads();

    float Rt[12];
    #pragma unroll
    for (int k = 0; k < 12; k++) Rt[k] = sRt[k];

    int i = blockIdx.x * blockDim.x + threadIdx.x;

    if (i < n_oct) {
        const char* p = xb + (size_t)96 * i;
        // Front-batch the 3 x 256-bit loads (MLP = 3).
        V8 a = ldg256_el(p);
        V8 b = ldg256_el(p + 32);
        V8 c = ldg256_el(p + 64);

        float f[24] = {
            __uint_as_float(a.r0), __uint_as_float(a.r1), __uint_as_float(a.r2),
            __uint_as_float(a.r3), __uint_as_float(a.r4), __uint_as_float(a.r5),
            __uint_as_float(a.r6), __uint_as_float(a.r7),
            __uint_as_float(b.r0), __uint_as_float(b.r1), __uint_as_float(b.r2),
            __uint_as_float(b.r3), __uint_as_float(b.r4), __uint_as_float(b.r5),
            __uint_as_float(b.r6), __uint_as_float(b.r7),
            __uint_as_float(c.r0), __uint_as_float(c.r1), __uint_as_float(c.r2),
            __uint_as_float(c.r3), __uint_as_float(c.r4), __uint_as_float(c.r5),
            __uint_as_float(c.r6), __uint_as_float(c.r7)
        };

        float g[24];
        #pragma unroll
        for (int k = 0; k < 8; k++) {
            float X = f[3 * k], Y = f[3 * k + 1], Z = f[3 * k + 2];
            g[3 * k + 0] = fmaf(Rt[0], X, fmaf(Rt[1], Y, fmaf(Rt[2], Z, Rt[9])));
            g[3 * k + 1] = fmaf(Rt[3], X, fmaf(Rt[4], Y, fmaf(Rt[5], Z, Rt[10])));
            g[3 * k + 2] = fmaf(Rt[6], X, fmaf(Rt[7], Y, fmaf(Rt[8], Z, Rt[11])));
        }

        char* q = ob + (size_t)96 * i;
        stg256_ef(q,      g);
        stg256_ef(q + 32, g + 8);
        stg256_ef(q + 64, g + 16);
    } else if (i == n_oct && n_tail > 0) {
        // Scalar tail (N % 8 points); dead for N = 8388608 but kept general.
        for (int k = 0; k < n_tail; k++) {
            int base = (n_oct * 8 + k) * 3;
            float X = x_tail[base + 0], Y = x_tail[base + 1],
                  Z = x_tail[base + 2];
            o_tail[base + 0] = fmaf(Rt[0], X, fmaf(Rt[1], Y, fmaf(Rt[2], Z, Rt[9])));
            o_tail[base + 1] = fmaf(Rt[3], X, fmaf(Rt[4], Y, fmaf(Rt[5], Z, Rt[10])));
            o_tail[base + 2] = fmaf(Rt[6], X, fmaf(Rt[7], Y, fmaf(Rt[8], Z, Rt[11])));
        }
    }
}

// ---------------------------------------------------------------------------
// Launch: single fused kernel, flat one-shot grid.
// ---------------------------------------------------------------------------
extern "C" void kernel_launch(void* const* d_in, const int* in_sizes, int n_in,
                              void* d_out, int out_size) {
    const float* pose = (const float*)d_in[0];  // (1, 6)
    const float* x    = (const float*)d_in[1];  // (N, 3)
    float* out = (float*)d_out;

    int n_points = in_sizes[1] / 3;
    int n_oct    = n_points / 8;
    int n_tail   = n_points % 8;

    const int threads = 256;
    int blocks = (n_oct + 1 + threads - 1) / threads;  // +1 thread for tail

    se3_fused_kernel<<<blocks, threads>>>(
        pose, (const char*)x, (char*)out, n_oct, x, out, n_tail);
}

// round 15
// speedup vs baseline: 1.1250x; 1.0055x over previous
#include <cuda_runtime.h>
#include <math.h>

// ---------------------------------------------------------------------------
// FINAL kernel (R14 champion + load hoist).
// Architecture settled over 14 rounds: 8 points/thread, 3 front-batched
// LDG.256 (L2::evict_last) + 24 FMA + 3 STG.256 (L2::evict_first), flat
// one-shot grid, fused fp32 SE(3) exp map. Steady-state floor: 192MB
// compulsory traffic at ~5.8TB/s mixed-stream + ~2us harness overhead.
// R15 micro-opt: loads are issued BEFORE the pose broadcast/barrier (they
// don't depend on R|t; ptxas can't hoist LDG across BAR itself), so the
// memory stream starts immediately at block launch instead of waiting
// ~200cyc for thread 0's sinf/cosf chain.
// ---------------------------------------------------------------------------
struct V8 { unsigned r0, r1, r2, r3, r4, r5, r6, r7; };

__device__ __forceinline__ V8 ldg256_el(const void* p) {
    V8 v;
    asm volatile("ld.global.nc.L2::evict_last.v8.b32 "
                 "{%0,%1,%2,%3,%4,%5,%6,%7}, [%8];"
                 : "=r"(v.r0), "=r"(v.r1), "=r"(v.r2), "=r"(v.r3),
                   "=r"(v.r4), "=r"(v.r5), "=r"(v.r6), "=r"(v.r7)
                 : "l"(p));
    return v;
}
__device__ __forceinline__ void stg256_ef(void* p, const float* g) {
    asm volatile("st.global.L2::evict_first.v8.b32 "
                 "[%0], {%1,%2,%3,%4,%5,%6,%7,%8};"
                 :: "l"(p),
                    "r"(__float_as_uint(g[0])), "r"(__float_as_uint(g[1])),
                    "r"(__float_as_uint(g[2])), "r"(__float_as_uint(g[3])),
                    "r"(__float_as_uint(g[4])), "r"(__float_as_uint(g[5])),
                    "r"(__float_as_uint(g[6])), "r"(__float_as_uint(g[7]))
                 : "memory");
}

__global__ void __launch_bounds__(256)
se3_fused_kernel(const float* __restrict__ pose,
                 const char* __restrict__ xb, char* __restrict__ ob,
                 int n_oct,
                 const float* __restrict__ x_tail, float* __restrict__ o_tail,
                 int n_tail) {
    __shared__ float sRt[12];

    const int i = blockIdx.x * blockDim.x + threadIdx.x;
    const bool body = (i < n_oct);

    // ---- 1. Issue the 3 x 256-bit loads FIRST (independent of R|t). ----
    V8 a, b, c;
    if (body) {
        const char* p = xb + (size_t)96 * i;
        a = ldg256_el(p);
        b = ldg256_el(p + 32);
        c = ldg256_el(p + 64);
    }

    // ---- 2. Pose -> R|t (thread 0), overlapped with the loads in flight. --
    if (threadIdx.x == 0) {
        float tx = pose[0], ty = pose[1], tz = pose[2];
        float px = pose[3], py = pose[4], pz = pose[5];
        float th2 = px * px + py * py + pz * pz;
        float A, B, C;
        if (th2 < 1e-8f) {
            A = 1.0f - th2 / 6.0f;
            B = 0.5f - th2 / 24.0f;
            C = 1.0f / 6.0f - th2 / 120.0f;
        } else {
            float th = sqrtf(th2);
            float s = sinf(th), cs = cosf(th);
            A = s / th;
            B = (1.0f - cs) / th2;
            C = (th - s) / (th2 * th);
        }
        // Phi^2 = phi*phi^T - th2*I (skew-symmetric identity)
        sRt[0] = 1.0f + B * (px * px - th2);
        sRt[1] = -A * pz + B * px * py;
        sRt[2] =  A * py + B * px * pz;
        sRt[3] =  A * pz + B * px * py;
        sRt[4] = 1.0f + B * (py * py - th2);
        sRt[5] = -A * px + B * py * pz;
        sRt[6] = -A * py + B * px * pz;
        sRt[7] =  A * px + B * py * pz;
        sRt[8] = 1.0f + B * (pz * pz - th2);

        float V0 = 1.0f + C * (px * px - th2);
        float V1 = -B * pz + C * px * py;
        float V2 =  B * py + C * px * pz;
        float V3 =  B * pz + C * px * py;
        float V4 = 1.0f + C * (py * py - th2);
        float V5 = -B * px + C * py * pz;
        float V6 = -B * py + C * px * pz;
        float V7 =  B * px + C * py * pz;
        float V8v = 1.0f + C * (pz * pz - th2);

        sRt[9]  = V0 * tx + V1 * ty + V2 * tz;
        sRt[10] = V3 * tx + V4 * ty + V5 * tz;
        sRt[11] = V6 * tx + V7 * ty + V8v * tz;
    }
    __syncthreads();

    float Rt[12];
    #pragma unroll
    for (int k = 0; k < 12; k++) Rt[k] = sRt[k];

    // ---- 3. Transform + store. ----
    if (body) {
        float f[24] = {
            __uint_as_float(a.r0), __uint_as_float(a.r1), __uint_as_float(a.r2),
            __uint_as_float(a.r3), __uint_as_float(a.r4), __uint_as_float(a.r5),
            __uint_as_float(a.r6), __uint_as_float(a.r7),
            __uint_as_float(b.r0), __uint_as_float(b.r1), __uint_as_float(b.r2),
            __uint_as_float(b.r3), __uint_as_float(b.r4), __uint_as_float(b.r5),
            __uint_as_float(b.r6), __uint_as_float(b.r7),
            __uint_as_float(c.r0), __uint_as_float(c.r1), __uint_as_float(c.r2),
            __uint_as_float(c.r3), __uint_as_float(c.r4), __uint_as_float(c.r5),
            __uint_as_float(c.r6), __uint_as_float(c.r7)
        };

        float g[24];
        #pragma unroll
        for (int k = 0; k < 8; k++) {
            float X = f[3 * k], Y = f[3 * k + 1], Z = f[3 * k + 2];
            g[3 * k + 0] = fmaf(Rt[0], X, fmaf(Rt[1], Y, fmaf(Rt[2], Z, Rt[9])));
            g[3 * k + 1] = fmaf(Rt[3], X, fmaf(Rt[4], Y, fmaf(Rt[5], Z, Rt[10])));
            g[3 * k + 2] = fmaf(Rt[6], X, fmaf(Rt[7], Y, fmaf(Rt[8], Z, Rt[11])));
        }

        char* q = ob + (size_t)96 * i;
        stg256_ef(q,      g);
        stg256_ef(q + 32, g + 8);
        stg256_ef(q + 64, g + 16);
    } else if (i == n_oct && n_tail > 0) {
        // Scalar tail (N % 8 points); dead for N = 8388608 but kept general.
        for (int k = 0; k < n_tail; k++) {
            int base = (n_oct * 8 + k) * 3;
            float X = x_tail[base + 0], Y = x_tail[base + 1],
                  Z = x_tail[base + 2];
            o_tail[base + 0] = fmaf(Rt[0], X, fmaf(Rt[1], Y, fmaf(Rt[2], Z, Rt[9])));
            o_tail[base + 1] = fmaf(Rt[3], X, fmaf(Rt[4], Y, fmaf(Rt[5], Z, Rt[10])));
            o_tail[base + 2] = fmaf(Rt[6], X, fmaf(Rt[7], Y, fmaf(Rt[8], Z, Rt[11])));
        }
    }
}

// ---------------------------------------------------------------------------
// Launch: single fused kernel, flat one-shot grid.
// ---------------------------------------------------------------------------
extern "C" void kernel_launch(void* const* d_in, const int* in_sizes, int n_in,
                              void* d_out, int out_size) {
    const float* pose = (const float*)d_in[0];  // (1, 6)
    const float* x    = (const float*)d_in[1];  // (N, 3)
    float* out = (float*)d_out;

    int n_points = in_sizes[1] / 3;
    int n_oct    = n_points / 8;
    int n_tail   = n_points % 8;

    const int threads = 256;
    int blocks = (n_oct + 1 + threads - 1) / threads;  // +1 thread for tail

    se3_fused_kernel<<<blocks, threads>>>(
        pose, (const char*)x, (char*)out, n_oct, x, out, n_tail);
}